// round 10
// baseline (speedup 1.0000x reference)
#include <cuda_runtime.h>
#include <cstdint>
#include <math.h>

using u64 = unsigned long long;

// Problem constants
constexpr int S = 4;
constexpr int T = 512;
constexpr int B = 16;
constexpr int D = 512;

constexpr int CPB     = 27;                 // block slots per batch
constexpr int NBLOCKS = CPB * B;            // 432 <= 148*3 slots, one wave
constexpr int NACC    = 16;                 // 16 squared distances (sp*4+sg)

constexpr int NTHREADS = 288;               // 8 compute warps + 1 producer warp
constexpr int NCOMPUTE = 256;

constexpr int NS          = 4;              // pipeline stages
constexpr int ROW_BYTES   = D * 4;          // 2048 B per (s,t) row
constexpr int STAGE_BYTES = 8 * ROW_BYTES;  // 4 pred + 4 gt rows = 16 KB
constexpr int SMEM_BYTES  = NS * STAGE_BYTES + NS * 16;

// Deterministic scratch
__device__ float g_part[B][CPB][NACC];
__device__ int   g_done = 0;

// ---------------- PTX helpers ----------------
__device__ __forceinline__ uint32_t smem_u32(const void* p) {
    uint32_t a;
    asm("{ .reg .u64 t; cvta.to.shared.u64 t, %1; cvt.u32.u64 %0, t; }" : "=r"(a) : "l"(p));
    return a;
}
__device__ __forceinline__ void mbar_init(uint32_t a, uint32_t cnt) {
    asm volatile("mbarrier.init.shared.b64 [%0], %1;" :: "r"(a), "r"(cnt) : "memory");
}
__device__ __forceinline__ void mbar_expect_tx(uint32_t a, uint32_t bytes) {
    asm volatile("mbarrier.arrive.expect_tx.shared.b64 _, [%0], %1;" :: "r"(a), "r"(bytes) : "memory");
}
__device__ __forceinline__ void mbar_arrive(uint32_t a) {
    asm volatile("mbarrier.arrive.shared.b64 _, [%0];" :: "r"(a) : "memory");
}
__device__ __forceinline__ void mbar_wait(uint32_t a, uint32_t phase) {
    asm volatile(
        "{\n\t.reg .pred P;\n\t"
        "W_%=:\n\t"
        "mbarrier.try_wait.parity.acquire.cta.shared::cta.b64 P, [%0], %1, 0x989680;\n\t"
        "@P bra.uni DN_%=;\n\t"
        "bra.uni W_%=;\n\t"
        "DN_%=:\n\t}"
        :: "r"(a), "r"(phase) : "memory");
}
__device__ __forceinline__ void bulk_g2s(uint32_t dst, const void* src, uint32_t bytes, uint32_t mbar) {
    asm volatile(
        "cp.async.bulk.shared::cta.global.mbarrier::complete_tx::bytes [%0], [%1], %2, [%3];"
        :: "r"(dst), "l"(src), "r"(bytes), "r"(mbar) : "memory");
}
__device__ __forceinline__ void fence_async() {
    asm volatile("fence.proxy.async.shared::cta;" ::: "memory");
}
__device__ __forceinline__ u64 lds64(uint32_t a) {
    u64 v;
    asm volatile("ld.shared.b64 %0, [%1];" : "=l"(v) : "r"(a));
    return v;
}
__device__ __forceinline__ void fma2(u64& acc, u64 a, u64 b) {
    asm("fma.rn.f32x2 %0, %1, %2, %0;" : "+l"(acc) : "l"(a), "l"(b));
}
__device__ __forceinline__ u64 add2(u64 a, u64 b) {
    u64 r;
    asm("add.rn.f32x2 %0, %1, %2;" : "=l"(r) : "l"(a), "l"(b));
    return r;
}
__device__ __forceinline__ float unpack_sum(u64 v) {
    float lo, hi;
    asm("mov.b64 {%0, %1}, %2;" : "=f"(lo), "=f"(hi) : "l"(v));
    return lo + hi;
}

// ---------------------------------------------------------------------------
// Warp-specialized fused kernel.
// Block (cx, b): batch b, rows t = cx + k*CPB (18 or 19 rows).
// Producer = warp 8 lane 0: uniform loop {wait empty, expect_tx, 8x bulk 2KB}.
// Consumers = warps 0-7 (256 threads): thread tid owns the float2 at byte
// offset tid*8 of every row -> 8 LDS.64 + 32 packed f32x2 ops per row.
// ---------------------------------------------------------------------------
__global__ __launch_bounds__(NTHREADS, 3) void minloss_fused(
    const float* __restrict__ preds,   // [S, T, B, D]
    const float* __restrict__ gts,     // [S, B, T, D]
    float* __restrict__ out)
{
    extern __shared__ char smem[];
    const int b    = blockIdx.y;
    const int cx   = blockIdx.x;
    const int tid  = threadIdx.x;
    const int warp = tid >> 5;
    const int lane = tid & 31;

    const uint32_t sbase = smem_u32(smem);
    const uint32_t mb    = sbase + NS * STAGE_BYTES;   // full[s]@+16s, empty[s]@+16s+8

    if (tid == 0) {
#pragma unroll
        for (int s = 0; s < NS; ++s) {
            mbar_init(mb + s * 16, 1);       // full: expect_tx arrive + tx bytes
            mbar_init(mb + s * 16 + 8, 8);   // empty: lane0 of each compute warp
        }
        fence_async();                        // init visible to async proxy
    }
    __syncthreads();

    const int niter = (T - cx + CPB - 1) / CPB;   // 18 or 19 rows

    u64 acc[NACC];
#pragma unroll
    for (int i = 0; i < NACC; ++i) acc[i] = 0ull;

    if (warp == 8) {
        // ---------------- producer (elected lane) ----------------
        if (lane == 0) {
            int st = 0; uint32_t eph = 1;     // flipped phase: first NS waits pass
            for (int it = 0; it < niter; ++it) {
                const uint32_t fullbar  = mb + st * 16;
                const uint32_t emptybar = fullbar + 8;
                mbar_wait(emptybar, eph);
                mbar_expect_tx(fullbar, STAGE_BYTES);
                const int t = cx + it * CPB;
                const uint32_t stage = sbase + st * STAGE_BYTES;
#pragma unroll
                for (int s = 0; s < 4; ++s) {
                    bulk_g2s(stage + s * ROW_BYTES,
                             preds + ((size_t)(s * T + t) * B + b) * D, ROW_BYTES, fullbar);
                    bulk_g2s(stage + (4 + s) * ROW_BYTES,
                             gts + ((size_t)(s * B + b) * T + t) * D, ROW_BYTES, fullbar);
                }
                if (++st == NS) { st = 0; eph ^= 1; }
            }
        }
    } else {
        // ---------------- consumers (256 threads) ----------------
        constexpr u64 SIGN2 = 0x8000000080000000ull;
        const uint32_t doff = tid * 8;
        int st = 0; uint32_t fph = 0;
        for (int it = 0; it < niter; ++it) {
            const uint32_t fullbar = mb + st * 16;
            mbar_wait(fullbar, fph);          // acquire: TMA data visible

            const uint32_t base = sbase + st * STAGE_BYTES + doff;
            u64 p[4], ng[4];
#pragma unroll
            for (int s = 0; s < 4; ++s) {
                p[s]  = lds64(base + s * ROW_BYTES);
                ng[s] = lds64(base + (4 + s) * ROW_BYTES) ^ SIGN2;   // -g
            }
#pragma unroll
            for (int sp = 0; sp < 4; ++sp)
#pragma unroll
                for (int sg = 0; sg < 4; ++sg) {
                    u64 d = add2(p[sp], ng[sg]);                     // p - g
                    fma2(acc[sp * 4 + sg], d, d);
                }

            __syncwarp();
            if (lane == 0) mbar_arrive(fullbar + 8);  // release empty
            if (++st == NS) { st = 0; fph ^= 1; }
        }
    }

    // ---------------- block reduction (all 9 warps) ----------------
    float vals[NACC];
#pragma unroll
    for (int i = 0; i < NACC; ++i) {
        vals[i] = unpack_sum(acc[i]);
#pragma unroll
        for (int off = 16; off > 0; off >>= 1)
            vals[i] += __shfl_down_sync(0xffffffffu, vals[i], off);
    }

    __shared__ float sacc[9][NACC];
    if (lane == 0) {
#pragma unroll
        for (int i = 0; i < NACC; ++i) sacc[warp][i] = vals[i];
    }
    __syncthreads();

    if (tid < NACC) {
        float a = 0.0f;
#pragma unroll
        for (int w = 0; w < 8; ++w) a += sacc[w][tid];   // warp 8 contributed 0
        g_part[b][cx][tid] = a;                          // deterministic overwrite
    }

    // ---- last-block ticket ----
    __threadfence();
    __syncthreads();
    __shared__ int s_last;
    if (tid == 0) {
        int ticket = atomicAdd(&g_done, 1);
        s_last = (ticket == NBLOCKS - 1);
    }
    __syncthreads();
    if (!s_last) return;

    // ================= Phase B (last block) =================
    __threadfence();                          // acquire

    __shared__ float s_final[B][NACC];
    if (warp < 8) {
#pragma unroll
        for (int k = 0; k < 2; ++k) {
            const int bb = warp * 2 + k;
            if (lane < NACC) {
                float a = 0.0f;
#pragma unroll
                for (int cc = 0; cc < CPB; ++cc)
                    a += __ldcg(&g_part[bb][cc][lane]);
                s_final[bb][lane] = a;
            }
        }
    }
    __syncthreads();

    __shared__ float batch_total[B];
    if (tid < B) {
        const float* a = s_final[tid];
        float dist[16];
#pragma unroll
        for (int i = 0; i < 16; ++i)
            dist[i] = sqrtf(fmaxf(a[i], 0.0f));

        const float INF = __int_as_float(0x7f800000);
        float total = 0.0f;
#pragma unroll
        for (int it = 0; it < 4; ++it) {
            int   m    = 0;
            float best = dist[0];
#pragma unroll
            for (int k = 1; k < 16; ++k)
                if (dist[k] < best) { best = dist[k]; m = k; }   // first occurrence
            total += best;
            const int r = m >> 2, cc = m & 3;
#pragma unroll
            for (int k = 0; k < 4; ++k) {
                dist[r * 4 + k]  = INF;
                dist[k * 4 + cc] = INF;
            }
        }
        batch_total[tid] = total;
    }
    __syncthreads();

    if (tid == 0) {
        float s = 0.0f;
#pragma unroll
        for (int bb = 0; bb < B; ++bb) s += batch_total[bb];
        out[0] = s;
        g_done = 0;                           // reset for next graph replay
    }
}

extern "C" void kernel_launch(void* const* d_in, const int* in_sizes, int n_in,
                              void* d_out, int out_size)
{
    const float* preds = (const float*)d_in[0];  // [4, 512, 16, 512]
    const float* gts   = (const float*)d_in[1];  // [4, 16, 512, 512]
    float* out = (float*)d_out;

    cudaFuncSetAttribute(minloss_fused,
                         cudaFuncAttributeMaxDynamicSharedMemorySize, SMEM_BYTES);
    dim3 grid(CPB, B);                           // (27, 16) = 432 blocks, one wave
    minloss_fused<<<grid, NTHREADS, SMEM_BYTES>>>(preds, gts, out);
}

// round 11
// speedup vs baseline: 1.7461x; 1.7461x over previous
#include <cuda_runtime.h>
#include <cstdint>
#include <math.h>

using u64 = unsigned long long;

// Problem constants
constexpr int S = 4;
constexpr int T = 512;
constexpr int B = 16;
constexpr int D = 512;

constexpr int CPB     = 37;            // block slots per batch
constexpr int NBLOCKS = CPB * B;       // 592 = 148 SMs * occ 4, one packed wave
constexpr int NACC    = 16;            // 16 squared distances (sp*4+sg)
constexpr int NLOC    = 8;             // per-thread accs (2 sp x 4 sg)

// Deterministic scratch
__device__ float g_part[B][CPB][NACC];
__device__ int   g_done = 0;

__device__ __forceinline__ void fma2(u64& acc, u64 a, u64 b) {
    asm("fma.rn.f32x2 %0, %1, %2, %0;" : "+l"(acc) : "l"(a), "l"(b));
}
__device__ __forceinline__ u64 add2(u64 a, u64 b) {
    u64 r;
    asm("add.rn.f32x2 %0, %1, %2;" : "=l"(r) : "l"(a), "l"(b));
    return r;
}
__device__ __forceinline__ u64 pack2(float lo, float hi) {
    u64 v;
    asm("mov.b64 %0, {%1, %2};" : "=l"(v) : "f"(lo), "f"(hi));
    return v;
}
__device__ __forceinline__ float unpack_sum(u64 v) {
    float lo, hi;
    asm("mov.b64 {%0, %1}, %2;" : "=f"(lo), "=f"(hi) : "l"(v));
    return lo + hi;
}

// ---------------------------------------------------------------------------
// Occ-4 fused kernel, accumulator-split across warp halves.
// Block (cx, b): batch b, rows t = cx + k*CPB (13 or 14 rows).
// Thread layout: lane128 = tid & 127 spans D via float4; half = tid>>7.
//   half 0 (warps 0-3): accumulates sp in {0,1};  half 1: sp in {2,3}.
// Each thread: 2 pred-row loads (__ldcs, unique) + 4 gt-row loads (shared with
// the other half -> L1 pending-hit merge, no extra DRAM), 8 u64 accumulators.
// ---------------------------------------------------------------------------
__global__ __launch_bounds__(256, 4) void minloss_fused(
    const float* __restrict__ preds,   // [S, T, B, D]
    const float* __restrict__ gts,     // [S, B, T, D]
    float* __restrict__ out)
{
    const int b    = blockIdx.y;
    const int cx   = blockIdx.x;
    const int tid  = threadIdx.x;
    const int lane128 = tid & 127;
    const int half    = tid >> 7;      // 0: sp={0,1}, 1: sp={2,3}
    const int sp0     = half * 2;

    const float4* pv = (const float4*)preds;   // 128 float4 per row
    const float4* gv = (const float4*)gts;

    u64 acc[NLOC];
#pragma unroll
    for (int i = 0; i < NLOC; ++i) acc[i] = 0ull;

    constexpr u64 SIGN2 = 0x8000000080000000ull;

    for (int t = cx; t < T; t += CPB) {
        float4 pr[2], gr[4];
#pragma unroll
        for (int k = 0; k < 2; ++k)
            pr[k] = __ldcs(pv + ((size_t)((sp0 + k) * T + t) * B + b) * 128 + lane128);
#pragma unroll
        for (int s = 0; s < 4; ++s)
            gr[s] = gv[((size_t)(s * B + b) * T + t) * 128 + lane128];

        u64 px[2][2], ng[4][2];
#pragma unroll
        for (int k = 0; k < 2; ++k) {
            px[k][0] = pack2(pr[k].x, pr[k].y);
            px[k][1] = pack2(pr[k].z, pr[k].w);
        }
#pragma unroll
        for (int s = 0; s < 4; ++s) {
            ng[s][0] = pack2(gr[s].x, gr[s].y) ^ SIGN2;   // -g
            ng[s][1] = pack2(gr[s].z, gr[s].w) ^ SIGN2;
        }
#pragma unroll
        for (int k = 0; k < 2; ++k)
#pragma unroll
            for (int sg = 0; sg < 4; ++sg) {
                u64 d0 = add2(px[k][0], ng[sg][0]);       // p - g
                fma2(acc[k * 4 + sg], d0, d0);
                u64 d1 = add2(px[k][1], ng[sg][1]);
                fma2(acc[k * 4 + sg], d1, d1);
            }
    }

    // ---------------- block reduction ----------------
    float vals[NLOC];
#pragma unroll
    for (int i = 0; i < NLOC; ++i) {
        vals[i] = unpack_sum(acc[i]);
#pragma unroll
        for (int off = 16; off > 0; off >>= 1)
            vals[i] += __shfl_down_sync(0xffffffffu, vals[i], off);
    }

    __shared__ float sacc[8][NLOC];
    const int warp = tid >> 5;
    const int lane = tid & 31;
    if (lane == 0) {
#pragma unroll
        for (int i = 0; i < NLOC; ++i) sacc[warp][i] = vals[i];
    }
    __syncthreads();

    // acc index i (0..15): sp = i>>2, sg = i&3.
    // Contributed by the 4 warps of half (sp>>1), local slot (sp&1)*4 + sg.
    if (tid < NACC) {
        const int sp = tid >> 2, sg = tid & 3;
        const int w0 = (sp >> 1) * 4;
        const int li = (sp & 1) * 4 + sg;
        float a = 0.0f;
#pragma unroll
        for (int w = 0; w < 4; ++w) a += sacc[w0 + w][li];
        g_part[b][cx][tid] = a;                       // deterministic overwrite
    }

    // ---- last-block ticket ----
    __threadfence();
    __syncthreads();
    __shared__ int s_last;
    if (tid == 0) {
        int ticket = atomicAdd(&g_done, 1);
        s_last = (ticket == NBLOCKS - 1);
    }
    __syncthreads();
    if (!s_last) return;

    // ================= Phase B (last block) =================
    __threadfence();                                  // acquire

    __shared__ float s_final[B][NACC];
#pragma unroll
    for (int k = 0; k < 2; ++k) {
        const int bb = warp * 2 + k;
        if (lane < NACC) {
            float a = 0.0f;
#pragma unroll
            for (int cc = 0; cc < CPB; ++cc)
                a += __ldcg(&g_part[bb][cc][lane]);   // L2, bypass stale L1
            s_final[bb][lane] = a;
        }
    }
    __syncthreads();

    __shared__ float batch_total[B];
    if (tid < B) {
        const float* a = s_final[tid];
        float dist[16];
#pragma unroll
        for (int i = 0; i < 16; ++i)
            dist[i] = sqrtf(fmaxf(a[i], 0.0f));       // d2 >= 0 by construction

        const float INF = __int_as_float(0x7f800000);
        float total = 0.0f;
#pragma unroll
        for (int it = 0; it < 4; ++it) {
            int   m    = 0;
            float best = dist[0];
#pragma unroll
            for (int k = 1; k < 16; ++k)
                if (dist[k] < best) { best = dist[k]; m = k; }   // first occurrence
            total += best;
            const int r = m >> 2, cc = m & 3;
#pragma unroll
            for (int k = 0; k < 4; ++k) {
                dist[r * 4 + k]  = INF;
                dist[k * 4 + cc] = INF;
            }
        }
        batch_total[tid] = total;
    }
    __syncthreads();

    if (tid == 0) {
        float s = 0.0f;
#pragma unroll
        for (int bb = 0; bb < B; ++bb) s += batch_total[bb];
        out[0] = s;
        g_done = 0;                                   // reset for next graph replay
    }
}

extern "C" void kernel_launch(void* const* d_in, const int* in_sizes, int n_in,
                              void* d_out, int out_size)
{
    const float* preds = (const float*)d_in[0];  // [4, 512, 16, 512]
    const float* gts   = (const float*)d_in[1];  // [4, 16, 512, 512]
    float* out = (float*)d_out;

    dim3 grid(CPB, B);                           // (37, 16) = 592 blocks, one wave
    minloss_fused<<<grid, 256>>>(preds, gts, out);
}

// round 13
// speedup vs baseline: 1.8539x; 1.0617x over previous
#include <cuda_runtime.h>
#include <cstdint>
#include <math.h>

using u64 = unsigned long long;

// Problem constants
constexpr int S = 4;
constexpr int T = 512;
constexpr int B = 16;
constexpr int D = 512;

constexpr int CPB     = 37;            // block slots per batch
constexpr int NBLOCKS = CPB * B;       // 592 = 148 SMs * occ 4, one packed wave
constexpr int NACC    = 16;            // 16 squared distances (sp*4+sg)
constexpr int NLOC    = 8;             // per-thread accs (2 sp x 4 sg)

// Deterministic scratch
__device__ float g_part[B][CPB][NACC];
__device__ int   g_done = 0;

__device__ __forceinline__ void fma2(u64& acc, u64 a, u64 b) {
    asm("fma.rn.f32x2 %0, %1, %2, %0;" : "+l"(acc) : "l"(a), "l"(b));
}
__device__ __forceinline__ u64 fma2v(u64 a, u64 b, u64 c) {   // a*b + c
    u64 r;
    asm("fma.rn.f32x2 %0, %1, %2, %3;" : "=l"(r) : "l"(a), "l"(b), "l"(c));
    return r;
}
__device__ __forceinline__ u64 pack2(float lo, float hi) {
    u64 v;
    asm("mov.b64 %0, {%1, %2};" : "=l"(v) : "f"(lo), "f"(hi));
    return v;
}
__device__ __forceinline__ float unpack_sum(u64 v) {
    float lo, hi;
    asm("mov.b64 {%0, %1}, %2;" : "=f"(lo), "=f"(hi) : "l"(v));
    return lo + hi;
}

// ---------------------------------------------------------------------------
// Occ-4 fused kernel, accumulator half-split (proven R11 layout) + fma-neg
// fusion + pointer-bump addressing.
// Block (cx, b): batch b, rows t = cx + k*CPB (13 or 14 rows).
// Thread layout: lane128 = tid & 127 spans D via float4; half = tid>>7
// computes sp in {2*half, 2*half+1} (8 packed accumulators).
// Per iter: 2 p-loads (__ldcs, unique) + 4 g-loads (shared across halves ->
// L1 pending-hit merge), then d = fma2(g, -1, p); acc = fma2(d, d, acc).
// ---------------------------------------------------------------------------
__global__ __launch_bounds__(256, 4) void minloss_fused(
    const float* __restrict__ preds,   // [S, T, B, D]
    const float* __restrict__ gts,     // [S, B, T, D]
    float* __restrict__ out)
{
    const int b    = blockIdx.y;
    const int cx   = blockIdx.x;
    const int tid  = threadIdx.x;
    const int lane128 = tid & 127;
    const int half    = tid >> 7;      // 0: sp={0,1}, 1: sp={2,3}
    const int sp0     = half * 2;

    // Pointer-bumped bases (float4 granularity)
    const float4* pp[2];
#pragma unroll
    for (int k = 0; k < 2; ++k)
        pp[k] = (const float4*)preds
              + ((size_t)((sp0 + k) * T + cx) * B + b) * 128 + lane128;
    const float4* gp[4];
#pragma unroll
    for (int s = 0; s < 4; ++s)
        gp[s] = (const float4*)gts
              + ((size_t)(s * B + b) * T + cx) * 128 + lane128;

    constexpr size_t PSTEP = (size_t)CPB * B * 128;   // float4s per t-step (preds)
    constexpr size_t GSTEP = (size_t)CPB * 128;       // float4s per t-step (gts)
    constexpr u64 NEG1 = 0xBF800000BF800000ull;       // (-1.f, -1.f)

    u64 acc[NLOC];
#pragma unroll
    for (int i = 0; i < NLOC; ++i) acc[i] = 0ull;

    const int niter = (T - cx + CPB - 1) / CPB;       // 13 or 14

    for (int it = 0; it < niter; ++it) {
        float4 pr[2], gr[4];
#pragma unroll
        for (int k = 0; k < 2; ++k) pr[k] = __ldcs(pp[k]);
#pragma unroll
        for (int s = 0; s < 4; ++s) gr[s] = gp[s][0];

        u64 px[2][2], gx[4][2];
#pragma unroll
        for (int k = 0; k < 2; ++k) {
            px[k][0] = pack2(pr[k].x, pr[k].y);
            px[k][1] = pack2(pr[k].z, pr[k].w);
        }
#pragma unroll
        for (int s = 0; s < 4; ++s) {
            gx[s][0] = pack2(gr[s].x, gr[s].y);
            gx[s][1] = pack2(gr[s].z, gr[s].w);
        }
#pragma unroll
        for (int k = 0; k < 2; ++k)
#pragma unroll
            for (int sg = 0; sg < 4; ++sg) {
                u64 d0 = fma2v(gx[sg][0], NEG1, px[k][0]);   // p - g
                fma2(acc[k * 4 + sg], d0, d0);
                u64 d1 = fma2v(gx[sg][1], NEG1, px[k][1]);
                fma2(acc[k * 4 + sg], d1, d1);
            }

#pragma unroll
        for (int k = 0; k < 2; ++k) pp[k] += PSTEP;
#pragma unroll
        for (int s = 0; s < 4; ++s) gp[s] += GSTEP;
    }

    // ---------------- block reduction ----------------
    float vals[NLOC];
#pragma unroll
    for (int i = 0; i < NLOC; ++i) {
        vals[i] = unpack_sum(acc[i]);
#pragma unroll
        for (int off = 16; off > 0; off >>= 1)
            vals[i] += __shfl_down_sync(0xffffffffu, vals[i], off);
    }

    __shared__ float sacc[8][NLOC];
    const int warp = tid >> 5;
    const int lane = tid & 31;
    if (lane == 0) {
#pragma unroll
        for (int i = 0; i < NLOC; ++i) sacc[warp][i] = vals[i];
    }
    __syncthreads();

    // acc index i (0..15): sp = i>>2, sg = i&3.
    // Contributed by the 4 warps of half (sp>>1), local slot (sp&1)*4 + sg.
    if (tid < NACC) {
        const int sp = tid >> 2, sg = tid & 3;
        const int w0 = (sp >> 1) * 4;
        const int li = (sp & 1) * 4 + sg;
        float a = 0.0f;
#pragma unroll
        for (int w = 0; w < 4; ++w) a += sacc[w0 + w][li];
        g_part[b][cx][tid] = a;                       // deterministic overwrite
    }

    // ---- last-block ticket ----
    __threadfence();
    __syncthreads();
    __shared__ int s_last;
    if (tid == 0) {
        int ticket = atomicAdd(&g_done, 1);
        s_last = (ticket == NBLOCKS - 1);
    }
    __syncthreads();
    if (!s_last) return;

    // ================= Phase B (last block) =================
    __threadfence();                                  // acquire

    __shared__ float s_final[B][NACC];
#pragma unroll
    for (int k = 0; k < 2; ++k) {
        const int bb = warp * 2 + k;
        if (lane < NACC) {
            float a = 0.0f;
#pragma unroll
            for (int cc = 0; cc < CPB; ++cc)
                a += __ldcg(&g_part[bb][cc][lane]);   // L2, bypass stale L1
            s_final[bb][lane] = a;
        }
    }
    __syncthreads();

    __shared__ float batch_total[B];
    if (tid < B) {
        const float* a = s_final[tid];
        float dist[16];
#pragma unroll
        for (int i = 0; i < 16; ++i)
            dist[i] = sqrtf(fmaxf(a[i], 0.0f));       // d2 >= 0 by construction

        const float INF = __int_as_float(0x7f800000);
        float total = 0.0f;
#pragma unroll
        for (int it = 0; it < 4; ++it) {
            int   m    = 0;
            float best = dist[0];
#pragma unroll
            for (int k = 1; k < 16; ++k)
                if (dist[k] < best) { best = dist[k]; m = k; }   // first occurrence
            total += best;
            const int r = m >> 2, cc = m & 3;
#pragma unroll
            for (int k = 0; k < 4; ++k) {
                dist[r * 4 + k]  = INF;
                dist[k * 4 + cc] = INF;
            }
        }
        batch_total[tid] = total;
    }
    __syncthreads();

    if (tid == 0) {
        float s = 0.0f;
#pragma unroll
        for (int bb = 0; bb < B; ++bb) s += batch_total[bb];
        out[0] = s;
        g_done = 0;                                   // reset for next graph replay
    }
}

extern "C" void kernel_launch(void* const* d_in, const int* in_sizes, int n_in,
                              void* d_out, int out_size)
{
    const float* preds = (const float*)d_in[0];  // [4, 512, 16, 512]
    const float* gts   = (const float*)d_in[1];  // [4, 16, 512, 512]
    float* out = (float*)d_out;

    dim3 grid(CPB, B);                           // (37, 16) = 592 blocks, one wave
    minloss_fused<<<grid, 256>>>(preds, gts, out);
}